// round 1
// baseline (speedup 1.0000x reference)
#include <cuda_runtime.h>

// ---------------- problem constants (fixed shapes) ----------------
#define B_   512
#define N_   100000
#define D_   256       // OBS_D
#define F_   256       // FEAT_D
#define HA_  128       // H*A = 16*8

// ---------------- GEMM tiling ----------------
#define BM 128
#define BN 128
#define BK 16
#define TM 8
#define TN 8

#define NT_SIM ((N_ + BN - 1) / BN)        // 782 column tiles over N
#define NCH    (((N_ / 4) + 255) / 256)    // 98 chunks of 1024 floats (exp pass)
#define KC     1040                        // split-K chunk (multiple of 16)
#define SPL    ((N_ + KC - 1) / KC)        // 97 splits

// ---------------- device scratch (static; no allocations) ----------------
__device__ float g_zt[(size_t)N_ * F_];          // encoded train  (102.4 MB)
__device__ float g_zq[(size_t)B_ * F_];          // encoded query
__device__ float g_pmax[(size_t)B_ * NT_SIM];    // per (row, colTile) max
__device__ float g_rmax[B_];                     // per-row max
__device__ float g_psum[(size_t)B_ * NCH];       // per (row, chunk) sum
__device__ float g_rinv[B_];                     // 1 / row-sum
__device__ float g_invT[1];                      // exp(-log_temperature)
__device__ float g_ppred[(size_t)SPL * B_ * HA_];// split-K pred partials (25 MB)

// ---------------- fast exp (FMA-pipe only; input <= ~2, mostly <= 0) ----------------
__device__ __forceinline__ float fexp(float x)
{
    // exp(x) = 2^(x*log2e); valid for x in [-87, ~60]; rel err ~1e-7
    x = fmaxf(x, -87.0f);
    float t = x * 1.4426950408889634f;
    float n = rintf(t);
    float f = t - n;
    float p =            1.5403530393e-4f;
    p = fmaf(p, f, 1.3333558146e-3f);
    p = fmaf(p, f, 9.6181291076e-3f);
    p = fmaf(p, f, 5.5504108664e-2f);
    p = fmaf(p, f, 2.4022650696e-1f);
    p = fmaf(p, f, 6.9314718056e-1f);
    p = fmaf(p, f, 1.0f);
    int ni = (int)n;                       // in [-126, 127] for clamped domain
    float s = __int_as_float((ni + 127) << 23);
    return p * s;
}

// ================= kernel 0: tiny prep (invT) =================
__global__ void prep_kernel(const float* __restrict__ logT)
{
    g_invT[0] = expf(-logT[0]);
}

// ================= kernel 1: encode  C[M,256] = A[M,256] @ W[256,256] =================
__global__ __launch_bounds__(256)
void encode_kernel(const float* __restrict__ A, const float* __restrict__ W,
                   float* __restrict__ C, int M)
{
    __shared__ float As[BK][BM + 4];
    __shared__ float Ws[BK][BN];
    const int tid = threadIdx.x;
    const int tx = tid & 15, ty = tid >> 4;
    const int rowBase = blockIdx.y * BM;
    const int colBase = blockIdx.x * BN;

    float acc[TM][TN];
#pragma unroll
    for (int i = 0; i < TM; i++)
#pragma unroll
        for (int j = 0; j < TN; j++) acc[i][j] = 0.f;

    for (int k0 = 0; k0 < D_; k0 += BK) {
#pragma unroll
        for (int l = 0; l < 2; l++) {               // A slab 128x16 -> transposed
            int idx = tid + l * 256;
            int r = idx >> 2;
            int c = (idx & 3) << 2;
            float4 v = make_float4(0.f, 0.f, 0.f, 0.f);
            int gr = rowBase + r;
            if (gr < M) v = *(const float4*)(A + (size_t)gr * D_ + k0 + c);
            As[c + 0][r] = v.x; As[c + 1][r] = v.y;
            As[c + 2][r] = v.z; As[c + 3][r] = v.w;
        }
#pragma unroll
        for (int l = 0; l < 2; l++) {               // W slab 16x128 direct
            int idx = tid + l * 256;
            int r = idx >> 5;
            int c = (idx & 31) << 2;
            *(float4*)&Ws[r][c] = *(const float4*)(W + (size_t)(k0 + r) * F_ + colBase + c);
        }
        __syncthreads();
#pragma unroll
        for (int k = 0; k < BK; k++) {
            float a[TM], b[TN];
            *(float4*)&a[0] = *(const float4*)&As[k][ty * TM];
            *(float4*)&a[4] = *(const float4*)&As[k][ty * TM + 4];
            *(float4*)&b[0] = *(const float4*)&Ws[k][tx * TN];
            *(float4*)&b[4] = *(const float4*)&Ws[k][tx * TN + 4];
#pragma unroll
            for (int i = 0; i < TM; i++)
#pragma unroll
                for (int j = 0; j < TN; j++)
                    acc[i][j] = fmaf(a[i], b[j], acc[i][j]);
        }
        __syncthreads();
    }
#pragma unroll
    for (int i = 0; i < TM; i++) {
        int gr = rowBase + ty * TM + i;
        if (gr < M) {
            float* cp = C + (size_t)gr * F_ + colBase + tx * TN;
            *(float4*)cp       = *(float4*)&acc[i][0];
            *(float4*)(cp + 4) = *(float4*)&acc[i][4];
        }
    }
}

// ================= kernel 2: sim (NT GEMM) + exclusion + tile row-max =================
// Wout[i,j] = dot(zq[i,:], zt[j,:]); Wout is the weights region of d_out (scratch)
__global__ __launch_bounds__(256)
void sim_kernel(const float* __restrict__ ZQ, const float* __restrict__ ZT,
                const long long* __restrict__ qidx, float* __restrict__ Wout)
{
    __shared__ float As[BK][BM + 4];
    __shared__ float Bs[BK][BN + 4];
    __shared__ int   s_q[BM];
    __shared__ float s_red[BM][17];
    const int tid = threadIdx.x;
    const int tx = tid & 15, ty = tid >> 4;
    const int rowBase = blockIdx.y * BM;     // query rows (always < 512)
    const int colBase = blockIdx.x * BN;     // train cols

    if (tid < BM) s_q[tid] = (int)qidx[rowBase + tid];

    float acc[TM][TN];
#pragma unroll
    for (int i = 0; i < TM; i++)
#pragma unroll
        for (int j = 0; j < TN; j++) acc[i][j] = 0.f;

    for (int k0 = 0; k0 < F_; k0 += BK) {
#pragma unroll
        for (int l = 0; l < 2; l++) {               // ZQ slab (rows always valid)
            int idx = tid + l * 256;
            int r = idx >> 2;
            int c = (idx & 3) << 2;
            float4 v = *(const float4*)(ZQ + (size_t)(rowBase + r) * F_ + k0 + c);
            As[c + 0][r] = v.x; As[c + 1][r] = v.y;
            As[c + 2][r] = v.z; As[c + 3][r] = v.w;
        }
#pragma unroll
        for (int l = 0; l < 2; l++) {               // ZT slab (guard rows >= N_)
            int idx = tid + l * 256;
            int r = idx >> 2;
            int c = (idx & 3) << 2;
            float4 v = make_float4(0.f, 0.f, 0.f, 0.f);
            int gr = colBase + r;
            if (gr < N_) v = *(const float4*)(ZT + (size_t)gr * F_ + k0 + c);
            Bs[c + 0][r] = v.x; Bs[c + 1][r] = v.y;
            Bs[c + 2][r] = v.z; Bs[c + 3][r] = v.w;
        }
        __syncthreads();
#pragma unroll
        for (int k = 0; k < BK; k++) {
            float a[TM], b[TN];
            *(float4*)&a[0] = *(const float4*)&As[k][ty * TM];
            *(float4*)&a[4] = *(const float4*)&As[k][ty * TM + 4];
            *(float4*)&b[0] = *(const float4*)&Bs[k][tx * TN];
            *(float4*)&b[4] = *(const float4*)&Bs[k][tx * TN + 4];
#pragma unroll
            for (int i = 0; i < TM; i++)
#pragma unroll
                for (int j = 0; j < TN; j++)
                    acc[i][j] = fmaf(a[i], b[j], acc[i][j]);
        }
        __syncthreads();
    }

    // epilogue: self-exclusion, store sim, per-(row,tile) max
#pragma unroll
    for (int i = 0; i < TM; i++) {
        const int lr = ty * TM + i;
        const int gr = rowBase + lr;
        const int qi = s_q[lr];
        float m = -3.0e38f;
#pragma unroll
        for (int j0 = 0; j0 < TN; j0 += 4) {
            int gc = colBase + tx * TN + j0;
            if (gc < N_) {                      // float4 is fully in/out (N_%4==0)
                float4 v;
                v.x = (gc + 0 == qi) ? -1e9f : acc[i][j0 + 0];
                v.y = (gc + 1 == qi) ? -1e9f : acc[i][j0 + 1];
                v.z = (gc + 2 == qi) ? -1e9f : acc[i][j0 + 2];
                v.w = (gc + 3 == qi) ? -1e9f : acc[i][j0 + 3];
                *(float4*)(Wout + (size_t)gr * N_ + gc) = v;
                m = fmaxf(m, fmaxf(fmaxf(v.x, v.y), fmaxf(v.z, v.w)));
            }
        }
        s_red[lr][tx] = m;
    }
    __syncthreads();
    if (tid < BM) {
        float m = s_red[tid][0];
#pragma unroll
        for (int t = 1; t < 16; t++) m = fmaxf(m, s_red[tid][t]);
        g_pmax[(size_t)(rowBase + tid) * NT_SIM + blockIdx.x] = m;
    }
}

// ================= kernel 3: reduce per-row max (deterministic tree) =================
__global__ __launch_bounds__(256)
void rowmax_kernel()
{
    const int row = blockIdx.x;
    const int tid = threadIdx.x;
    float m = -3.0e38f;
    for (int t = tid; t < NT_SIM; t += 256)
        m = fmaxf(m, g_pmax[(size_t)row * NT_SIM + t]);
    __shared__ float sm[256];
    sm[tid] = m; __syncthreads();
    for (int s = 128; s > 0; s >>= 1) {
        if (tid < s) sm[tid] = fmaxf(sm[tid], sm[tid + s]);
        __syncthreads();
    }
    if (tid == 0) g_rmax[row] = sm[0];
}

// ================= kernel 4: exp pass (in place) + per-chunk sums =================
__global__ __launch_bounds__(256)
void exp_kernel(float* __restrict__ Wbuf)
{
    const int row = blockIdx.y;
    const int tid = threadIdx.x;
    const float invT = g_invT[0];
    const float m = g_rmax[row];
    const int i4 = blockIdx.x * 256 + tid;       // float4 index in row
    float ls = 0.f;
    if (i4 < N_ / 4) {
        float4 v = *(float4*)(Wbuf + (size_t)row * N_ + (size_t)i4 * 4);
        v.x = fexp((v.x - m) * invT);
        v.y = fexp((v.y - m) * invT);
        v.z = fexp((v.z - m) * invT);
        v.w = fexp((v.w - m) * invT);
        *(float4*)(Wbuf + (size_t)row * N_ + (size_t)i4 * 4) = v;
        ls = (v.x + v.y) + (v.z + v.w);
    }
    __shared__ float sm[256];
    sm[tid] = ls; __syncthreads();
    for (int s = 128; s > 0; s >>= 1) {
        if (tid < s) sm[tid] += sm[tid + s];
        __syncthreads();
    }
    if (tid == 0) g_psum[(size_t)row * NCH + blockIdx.x] = sm[0];
}

// ================= kernel 5: per-row 1/sum (sequential = deterministic) =================
__global__ __launch_bounds__(256)
void rowsum_kernel()
{
    const int row = blockIdx.x * 256 + threadIdx.x;
    if (row < B_) {
        float s = 0.f;
        for (int c = 0; c < NCH; c++) s += g_psum[(size_t)row * NCH + c];
        g_rinv[row] = 1.f / s;
    }
}

// ===== kernel 6: split-K pred GEMM; normalizes + writes final weights en route =====
// pred_partial[s] = w[rows, kchunk] @ actions[kchunk, 128]
__global__ __launch_bounds__(256)
void pred_kernel(const float* __restrict__ Act, float* __restrict__ Wbuf)
{
    __shared__ float Ws[BK][BM + 4];
    __shared__ float Bs[BK][HA_];
    __shared__ float s_inv[BM];
    const int tid = threadIdx.x;
    const int tx = tid & 15, ty = tid >> 4;
    const int rowBase = blockIdx.y * BM;
    const int kBase = blockIdx.x * KC;
    const int kEnd = min(kBase + KC, N_);        // chunk length is multiple of 16
    if (tid < BM) s_inv[tid] = g_rinv[rowBase + tid];
    __syncthreads();

    float acc[TM][TN];
#pragma unroll
    for (int i = 0; i < TM; i++)
#pragma unroll
        for (int j = 0; j < TN; j++) acc[i][j] = 0.f;

    for (int k0 = kBase; k0 < kEnd; k0 += BK) {
#pragma unroll
        for (int l = 0; l < 2; l++) {            // e slab: normalize, write back, stage
            int idx = tid + l * 256;
            int r = idx >> 2;
            int c = (idx & 3) << 2;
            int gk = k0 + c;
            float* p = Wbuf + (size_t)(rowBase + r) * N_ + gk;
            float4 v = *(float4*)p;
            float inv = s_inv[r];
            v.x *= inv; v.y *= inv; v.z *= inv; v.w *= inv;
            *(float4*)p = v;                     // final normalized weight output
            Ws[c + 0][r] = v.x; Ws[c + 1][r] = v.y;
            Ws[c + 2][r] = v.z; Ws[c + 3][r] = v.w;
        }
#pragma unroll
        for (int l = 0; l < 2; l++) {            // actions slab 16x128 direct
            int idx = tid + l * 256;
            int r = idx >> 5;
            int c = (idx & 31) << 2;
            *(float4*)&Bs[r][c] = *(const float4*)(Act + (size_t)(k0 + r) * HA_ + c);
        }
        __syncthreads();
#pragma unroll
        for (int k = 0; k < BK; k++) {
            float a[TM], b[TN];
            *(float4*)&a[0] = *(const float4*)&Ws[k][ty * TM];
            *(float4*)&a[4] = *(const float4*)&Ws[k][ty * TM + 4];
            *(float4*)&b[0] = *(const float4*)&Bs[k][tx * TN];
            *(float4*)&b[4] = *(const float4*)&Bs[k][tx * TN + 4];
#pragma unroll
            for (int i = 0; i < TM; i++)
#pragma unroll
                for (int j = 0; j < TN; j++)
                    acc[i][j] = fmaf(a[i], b[j], acc[i][j]);
        }
        __syncthreads();
    }

    float* pp = g_ppred + (size_t)blockIdx.x * (B_ * HA_);
#pragma unroll
    for (int i = 0; i < TM; i++) {
        int row = rowBase + ty * TM + i;
        float* cp = pp + (size_t)row * HA_ + tx * TN;
        *(float4*)cp       = *(float4*)&acc[i][0];
        *(float4*)(cp + 4) = *(float4*)&acc[i][4];
    }
}

// ================= kernel 7: deterministic split-K reduction -> pred =================
__global__ __launch_bounds__(256)
void predsum_kernel(float* __restrict__ outPred)
{
    const int idx = blockIdx.x * 256 + threadIdx.x;
    if (idx < B_ * HA_) {
        float s = 0.f;
        for (int t = 0; t < SPL; t++)
            s += g_ppred[(size_t)t * (B_ * HA_) + idx];
        outPred[idx] = s;
    }
}

// ================= launch =================
extern "C" void kernel_launch(void* const* d_in, const int* in_sizes, int n_in,
                              void* d_out, int out_size)
{
    const float*     query_obs     = (const float*)d_in[0];
    const long long* query_indices = (const long long*)d_in[1];
    const float*     W_enc         = (const float*)d_in[2];
    const float*     train_obs     = (const float*)d_in[3];
    const float*     train_actions = (const float*)d_in[4];
    const float*     logT          = (const float*)d_in[5];

    float* out_pred = (float*)d_out;                       // (512, 16, 8)
    float* out_w    = (float*)d_out + (size_t)B_ * HA_;    // (512, 100000)

    float* zt_p; cudaGetSymbolAddress((void**)&zt_p, g_zt);
    float* zq_p; cudaGetSymbolAddress((void**)&zq_p, g_zq);

    dim3 blk(256);

    prep_kernel<<<1, 1>>>(logT);
    encode_kernel<<<dim3(F_ / BN, (N_ + BM - 1) / BM), blk>>>(train_obs, W_enc, zt_p, N_);
    encode_kernel<<<dim3(F_ / BN, (B_ + BM - 1) / BM), blk>>>(query_obs, W_enc, zq_p, B_);
    sim_kernel<<<dim3(NT_SIM, B_ / BM), blk>>>(zq_p, zt_p, query_indices, out_w);
    rowmax_kernel<<<B_, blk>>>();
    exp_kernel<<<dim3(NCH, B_), blk>>>(out_w);
    rowsum_kernel<<<(B_ + 255) / 256, blk>>>();
    pred_kernel<<<dim3(SPL, B_ / BM), blk>>>(train_actions, out_w);
    predsum_kernel<<<(B_ * HA_ + 255) / 256, blk>>>(out_pred);
}

// round 2
// speedup vs baseline: 1.2733x; 1.2733x over previous
#include <cuda_runtime.h>

// ---------------- problem constants (fixed shapes) ----------------
#define B_   512
#define N_   100000
#define NPAD 100096    // N padded to multiple of 128 (zero-filled tail)
#define D_   256       // OBS_D
#define F_   256       // FEAT_D
#define HA_  128       // H*A

// ---------------- GEMM tiling ----------------
#define BM 128
#define BN 128
#define BK 16

#define NT_SIM ((N_ + BN - 1) / BN)        // 782
#define NCH    (((N_ / 4) + 255) / 256)    // 98
#define KC     1040
#define SPL    ((N_ + KC - 1) / KC)        // 97

// ---------------- device scratch ----------------
__device__ float g_ztT[(size_t)F_ * NPAD];       // transposed encoded train [F][NPAD]
__device__ float g_zqT[(size_t)F_ * B_];         // transposed encoded query [F][B]
__device__ float g_pmax[(size_t)B_ * NT_SIM];
__device__ float g_rmax[B_];
__device__ float g_psum[(size_t)B_ * NCH];
__device__ float g_rinv[B_];
__device__ float g_invT[1];
__device__ float g_ppred[(size_t)SPL * B_ * HA_];

typedef unsigned long long ull;

// ---------------- f32x2 packed-FMA helpers (Blackwell) ----------------
__device__ __forceinline__ ull pack2(float lo, float hi) {
    ull r; asm("mov.b64 %0, {%1,%2};" : "=l"(r) : "f"(lo), "f"(hi)); return r;
}
__device__ __forceinline__ float2 unpack2(ull v) {
    float2 f; asm("mov.b64 {%0,%1}, %2;" : "=f"(f.x), "=f"(f.y) : "l"(v)); return f;
}
__device__ __forceinline__ void fma2(ull& d, ull a, ull b) {
    asm("fma.rn.f32x2 %0, %1, %2, %0;" : "+l"(d) : "l"(a), "l"(b));
}

// ---------------- cp.async helpers ----------------
__device__ __forceinline__ unsigned su(const void* p) {
    return (unsigned)__cvta_generic_to_shared(p);
}
__device__ __forceinline__ void cp16(unsigned d, const void* s) {
    asm volatile("cp.async.ca.shared.global [%0], [%1], 16;" :: "r"(d), "l"(s));
}
__device__ __forceinline__ void cpcommit() { asm volatile("cp.async.commit_group;"); }
__device__ __forceinline__ void cpwait0()  { asm volatile("cp.async.wait_group 0;"); }

// ---------------- fast exp (FMA pipe only) ----------------
__device__ __forceinline__ float fexp(float x)
{
    x = fmaxf(x, -87.0f);
    float t = x * 1.4426950408889634f;
    float n = rintf(t);
    float f = t - n;
    float p =            1.5403530393e-4f;
    p = fmaf(p, f, 1.3333558146e-3f);
    p = fmaf(p, f, 9.6181291076e-3f);
    p = fmaf(p, f, 5.5504108664e-2f);
    p = fmaf(p, f, 2.4022650696e-1f);
    p = fmaf(p, f, 6.9314718056e-1f);
    p = fmaf(p, f, 1.0f);
    int ni = (int)n;
    float s = __int_as_float((ni + 127) << 23);
    return p * s;
}

// ================= kernel 0: prep =================
__global__ void prep_kernel(const float* __restrict__ logT)
{
    g_invT[0] = expf(-logT[0]);
}

// ================= kernel 1: encode with TRANSPOSED output =================
// CT[f][m] = sum_k A[m][k] * W[k][f]
__global__ __launch_bounds__(256, 2)
void encodeT_kernel(const float* __restrict__ A, const float* __restrict__ W,
                    float* __restrict__ CT, int M, size_t ldct)
{
    __shared__ __align__(16) float As[2][BK][BM + 4];
    __shared__ __align__(16) float Ws[2][BK][BN];
    const int tid = threadIdx.x, tx = tid & 15, ty = tid >> 4;
    const int rowBase = blockIdx.y * BM, colBase = blockIdx.x * BN;

    ull acc[8][4];
#pragma unroll
    for (int i = 0; i < 8; i++)
#pragma unroll
        for (int j = 0; j < 4; j++) acc[i][j] = 0ull;

    const int r4 = tid >> 2, c4 = (tid & 3) << 2;     // A staging coords
    const int rw = tid >> 5, ow = (tid & 31) << 2;    // cp.async coords
    float4 pa[2];

    auto ldA = [&](int k0) {
#pragma unroll
        for (int l = 0; l < 2; l++) {
            int gr = rowBase + r4 + l * 64;
            pa[l] = make_float4(0.f, 0.f, 0.f, 0.f);
            if (gr < M) pa[l] = *(const float4*)(A + (size_t)gr * D_ + k0 + c4);
        }
    };
    auto stsA = [&](int buf) {
#pragma unroll
        for (int l = 0; l < 2; l++) {
            int r = r4 + l * 64;
            As[buf][c4 + 0][r] = pa[l].x; As[buf][c4 + 1][r] = pa[l].y;
            As[buf][c4 + 2][r] = pa[l].z; As[buf][c4 + 3][r] = pa[l].w;
        }
    };
    auto cpW = [&](int buf, int k0) {
#pragma unroll
        for (int l = 0; l < 2; l++)
            cp16(su(&Ws[buf][rw + l * 8][ow]),
                 W + (size_t)(k0 + rw + l * 8) * F_ + colBase + ow);
        cpcommit();
    };

    ldA(0); cpW(0, 0);
    stsA(0); cpwait0(); __syncthreads();

#pragma unroll 2
    for (int it = 0; it < D_ / BK; it++) {
        const int cur = it & 1;
        if (it + 1 < D_ / BK) { ldA((it + 1) * BK); cpW(cur ^ 1, (it + 1) * BK); }
#pragma unroll
        for (int k = 0; k < BK; k++) {
            float4 a0 = *(const float4*)&As[cur][k][ty * 8];
            float4 a1 = *(const float4*)&As[cur][k][ty * 8 + 4];
            ulonglong2 b0 = *(const ulonglong2*)&Ws[cur][k][tx * 8];
            ulonglong2 b1 = *(const ulonglong2*)&Ws[cur][k][tx * 8 + 4];
            float av[8] = {a0.x, a0.y, a0.z, a0.w, a1.x, a1.y, a1.z, a1.w};
#pragma unroll
            for (int i = 0; i < 8; i++) {
                ull ap = pack2(av[i], av[i]);
                fma2(acc[i][0], ap, b0.x); fma2(acc[i][1], ap, b0.y);
                fma2(acc[i][2], ap, b1.x); fma2(acc[i][3], ap, b1.y);
            }
        }
        if (it + 1 < D_ / BK) { stsA(cur ^ 1); cpwait0(); }
        __syncthreads();
    }

    // transposed store: CT[f][m], m contiguous
    float cr[8][8];
#pragma unroll
    for (int i = 0; i < 8; i++)
#pragma unroll
        for (int j2 = 0; j2 < 4; j2++) {
            float2 u = unpack2(acc[i][j2]);
            cr[i][2 * j2] = u.x; cr[i][2 * j2 + 1] = u.y;
        }
    const int m0 = rowBase + ty * 8;
    if (m0 < M) {
#pragma unroll
        for (int j = 0; j < 8; j++) {
            size_t f = (size_t)(colBase + tx * 8 + j);
            float4 v0 = make_float4(cr[0][j], cr[1][j], cr[2][j], cr[3][j]);
            float4 v1 = make_float4(cr[4][j], cr[5][j], cr[6][j], cr[7][j]);
            *(float4*)(CT + f * ldct + m0)     = v0;
            *(float4*)(CT + f * ldct + m0 + 4) = v1;
        }
    }
}

// ================= kernel 2: sim (both operands cp.async from transposed) =================
__global__ __launch_bounds__(256, 2)
void sim_kernel(const float* __restrict__ ZQT, const float* __restrict__ ZTT,
                const long long* __restrict__ qidx, float* __restrict__ Wout)
{
    __shared__ __align__(16) float As[2][BK][BM];
    __shared__ __align__(16) float Bs[2][BK][BN];
    __shared__ int   s_q[BM];
    __shared__ float s_red[BM][17];
    const int tid = threadIdx.x, tx = tid & 15, ty = tid >> 4;
    const int rowBase = blockIdx.y * BM, colBase = blockIdx.x * BN;
    if (tid < BM) s_q[tid] = (int)qidx[rowBase + tid];

    const int rw = tid >> 5, ow = (tid & 31) << 2;
    auto loadSlabs = [&](int buf, int k0) {
#pragma unroll
        for (int l = 0; l < 2; l++) {
            int r = rw + 8 * l;
            cp16(su(&As[buf][r][ow]), ZQT + (size_t)(k0 + r) * B_   + rowBase + ow);
            cp16(su(&Bs[buf][r][ow]), ZTT + (size_t)(k0 + r) * NPAD + colBase + ow);
        }
        cpcommit();
    };

    ull acc[8][4];
#pragma unroll
    for (int i = 0; i < 8; i++)
#pragma unroll
        for (int j = 0; j < 4; j++) acc[i][j] = 0ull;

    loadSlabs(0, 0);
    cpwait0(); __syncthreads();

#pragma unroll 2
    for (int it = 0; it < F_ / BK; it++) {
        const int cur = it & 1;
        if (it + 1 < F_ / BK) loadSlabs(cur ^ 1, (it + 1) * BK);
#pragma unroll
        for (int k = 0; k < BK; k++) {
            float4 a0 = *(const float4*)&As[cur][k][ty * 8];
            float4 a1 = *(const float4*)&As[cur][k][ty * 8 + 4];
            ulonglong2 b0 = *(const ulonglong2*)&Bs[cur][k][tx * 8];
            ulonglong2 b1 = *(const ulonglong2*)&Bs[cur][k][tx * 8 + 4];
            float av[8] = {a0.x, a0.y, a0.z, a0.w, a1.x, a1.y, a1.z, a1.w};
#pragma unroll
            for (int i = 0; i < 8; i++) {
                ull ap = pack2(av[i], av[i]);
                fma2(acc[i][0], ap, b0.x); fma2(acc[i][1], ap, b0.y);
                fma2(acc[i][2], ap, b1.x); fma2(acc[i][3], ap, b1.y);
            }
        }
        if (it + 1 < F_ / BK) cpwait0();
        __syncthreads();
    }

    // epilogue: exclusion, store sim, per-(row,tile) max
#pragma unroll
    for (int i = 0; i < 8; i++) {
        const int lr = ty * 8 + i;
        const int gr = rowBase + lr;
        const int qi = s_q[lr];
        float2 u0 = unpack2(acc[i][0]), u1 = unpack2(acc[i][1]);
        float2 u2 = unpack2(acc[i][2]), u3 = unpack2(acc[i][3]);
        float m = -3.0e38f;
        int gc0 = colBase + tx * 8;
        if (gc0 < N_) {
            float4 v;
            v.x = (gc0 + 0 == qi) ? -1e9f : u0.x;
            v.y = (gc0 + 1 == qi) ? -1e9f : u0.y;
            v.z = (gc0 + 2 == qi) ? -1e9f : u1.x;
            v.w = (gc0 + 3 == qi) ? -1e9f : u1.y;
            *(float4*)(Wout + (size_t)gr * N_ + gc0) = v;
            m = fmaxf(fmaxf(v.x, v.y), fmaxf(v.z, v.w));
        }
        int gc1 = gc0 + 4;
        if (gc1 < N_) {
            float4 v;
            v.x = (gc1 + 0 == qi) ? -1e9f : u2.x;
            v.y = (gc1 + 1 == qi) ? -1e9f : u2.y;
            v.z = (gc1 + 2 == qi) ? -1e9f : u3.x;
            v.w = (gc1 + 3 == qi) ? -1e9f : u3.y;
            *(float4*)(Wout + (size_t)gr * N_ + gc1) = v;
            m = fmaxf(m, fmaxf(fmaxf(v.x, v.y), fmaxf(v.z, v.w)));
        }
        s_red[lr][tx] = m;
    }
    __syncthreads();
    if (tid < BM) {
        float m = s_red[tid][0];
#pragma unroll
        for (int t = 1; t < 16; t++) m = fmaxf(m, s_red[tid][t]);
        g_pmax[(size_t)(rowBase + tid) * NT_SIM + blockIdx.x] = m;
    }
}

// ================= kernel 3: per-row max =================
__global__ __launch_bounds__(256)
void rowmax_kernel()
{
    const int row = blockIdx.x;
    const int tid = threadIdx.x;
    float m = -3.0e38f;
    for (int t = tid; t < NT_SIM; t += 256)
        m = fmaxf(m, g_pmax[(size_t)row * NT_SIM + t]);
    __shared__ float sm[256];
    sm[tid] = m; __syncthreads();
    for (int s = 128; s > 0; s >>= 1) {
        if (tid < s) sm[tid] = fmaxf(sm[tid], sm[tid + s]);
        __syncthreads();
    }
    if (tid == 0) g_rmax[row] = sm[0];
}

// ================= kernel 4: exp pass (in place) + chunk sums =================
__global__ __launch_bounds__(256)
void exp_kernel(float* __restrict__ Wbuf)
{
    const int row = blockIdx.y;
    const int tid = threadIdx.x;
    const float invT = g_invT[0];
    const float m = g_rmax[row];
    const int i4 = blockIdx.x * 256 + tid;
    float ls = 0.f;
    if (i4 < N_ / 4) {
        float4 v = *(float4*)(Wbuf + (size_t)row * N_ + (size_t)i4 * 4);
        v.x = fexp((v.x - m) * invT);
        v.y = fexp((v.y - m) * invT);
        v.z = fexp((v.z - m) * invT);
        v.w = fexp((v.w - m) * invT);
        *(float4*)(Wbuf + (size_t)row * N_ + (size_t)i4 * 4) = v;
        ls = (v.x + v.y) + (v.z + v.w);
    }
    __shared__ float sm[256];
    sm[tid] = ls; __syncthreads();
    for (int s = 128; s > 0; s >>= 1) {
        if (tid < s) sm[tid] += sm[tid + s];
        __syncthreads();
    }
    if (tid == 0) g_psum[(size_t)row * NCH + blockIdx.x] = sm[0];
}

// ================= kernel 5: per-row 1/sum =================
__global__ __launch_bounds__(256)
void rowsum_kernel()
{
    const int row = blockIdx.x * 256 + threadIdx.x;
    if (row < B_) {
        float s = 0.f;
        for (int c = 0; c < NCH; c++) s += g_psum[(size_t)row * NCH + c];
        g_rinv[row] = 1.f / s;
    }
}

// ===== kernel 6: split-K pred GEMM; normalizes + writes final weights en route =====
__global__ __launch_bounds__(256, 2)
void pred_kernel(const float* __restrict__ Act, float* __restrict__ Wbuf)
{
    __shared__ __align__(16) float Ws[2][BK][BM + 4];
    __shared__ __align__(16) float Bs[2][BK][HA_];
    __shared__ float s_inv[BM];
    const int tid = threadIdx.x, tx = tid & 15, ty = tid >> 4;
    const int rowBase = blockIdx.y * BM;
    const int kBase = blockIdx.x * KC;
    const int nIt = (min(kBase + KC, N_) - kBase) / BK;
    if (tid < BM) s_inv[tid] = g_rinv[rowBase + tid];

    const int r4 = tid >> 2, c4 = (tid & 3) << 2;
    const int rw = tid >> 5, ow = (tid & 31) << 2;
    float4 pw[2];

    auto ldW = [&](int k0) {
#pragma unroll
        for (int l = 0; l < 2; l++) {
            int r = r4 + l * 64;
            pw[l] = *(const float4*)(Wbuf + (size_t)(rowBase + r) * N_ + k0 + c4);
        }
    };
    auto stsW = [&](int buf, int k0) {
#pragma unroll
        for (int l = 0; l < 2; l++) {
            int r = r4 + l * 64;
            float inv = s_inv[r];
            float4 v = pw[l];
            v.x *= inv; v.y *= inv; v.z *= inv; v.w *= inv;
            *(float4*)(Wbuf + (size_t)(rowBase + r) * N_ + k0 + c4) = v;  // final weights
            Ws[buf][c4 + 0][r] = v.x; Ws[buf][c4 + 1][r] = v.y;
            Ws[buf][c4 + 2][r] = v.z; Ws[buf][c4 + 3][r] = v.w;
        }
    };
    auto cpB = [&](int buf, int k0) {
#pragma unroll
        for (int l = 0; l < 2; l++) {
            int r = rw + 8 * l;
            cp16(su(&Bs[buf][r][ow]), Act + (size_t)(k0 + r) * HA_ + ow);
        }
        cpcommit();
    };

    ull acc[8][4];
#pragma unroll
    for (int i = 0; i < 8; i++)
#pragma unroll
        for (int j = 0; j < 4; j++) acc[i][j] = 0ull;

    ldW(kBase); cpB(0, kBase);
    __syncthreads();                 // s_inv visible before staging
    stsW(0, kBase); cpwait0(); __syncthreads();

    for (int it = 0; it < nIt; it++) {
        const int cur = it & 1;
        const int k1 = kBase + (it + 1) * BK;
        if (it + 1 < nIt) { ldW(k1); cpB(cur ^ 1, k1); }
#pragma unroll
        for (int k = 0; k < BK; k++) {
            float4 a0 = *(const float4*)&Ws[cur][k][ty * 8];
            float4 a1 = *(const float4*)&Ws[cur][k][ty * 8 + 4];
            ulonglong2 b0 = *(const ulonglong2*)&Bs[cur][k][tx * 8];
            ulonglong2 b1 = *(const ulonglong2*)&Bs[cur][k][tx * 8 + 4];
            float av[8] = {a0.x, a0.y, a0.z, a0.w, a1.x, a1.y, a1.z, a1.w};
#pragma unroll
            for (int i = 0; i < 8; i++) {
                ull ap = pack2(av[i], av[i]);
                fma2(acc[i][0], ap, b0.x); fma2(acc[i][1], ap, b0.y);
                fma2(acc[i][2], ap, b1.x); fma2(acc[i][3], ap, b1.y);
            }
        }
        if (it + 1 < nIt) { stsW(cur ^ 1, k1); cpwait0(); }
        __syncthreads();
    }

    float* pp = g_ppred + (size_t)blockIdx.x * (B_ * HA_);
#pragma unroll
    for (int i = 0; i < 8; i++) {
        int row = rowBase + ty * 8 + i;
        float2 u0 = unpack2(acc[i][0]), u1 = unpack2(acc[i][1]);
        float2 u2 = unpack2(acc[i][2]), u3 = unpack2(acc[i][3]);
        float* cp = pp + (size_t)row * HA_ + tx * 8;
        *(float4*)cp       = make_float4(u0.x, u0.y, u1.x, u1.y);
        *(float4*)(cp + 4) = make_float4(u2.x, u2.y, u3.x, u3.y);
    }
}

// ================= kernel 7: deterministic split-K reduction =================
__global__ __launch_bounds__(256)
void predsum_kernel(float* __restrict__ outPred)
{
    const int idx = blockIdx.x * 256 + threadIdx.x;
    if (idx < B_ * HA_) {
        float s = 0.f;
        for (int t = 0; t < SPL; t++)
            s += g_ppred[(size_t)t * (B_ * HA_) + idx];
        outPred[idx] = s;
    }
}

// ================= launch =================
extern "C" void kernel_launch(void* const* d_in, const int* in_sizes, int n_in,
                              void* d_out, int out_size)
{
    const float*     query_obs     = (const float*)d_in[0];
    const long long* query_indices = (const long long*)d_in[1];
    const float*     W_enc         = (const float*)d_in[2];
    const float*     train_obs     = (const float*)d_in[3];
    const float*     train_actions = (const float*)d_in[4];
    const float*     logT          = (const float*)d_in[5];

    float* out_pred = (float*)d_out;
    float* out_w    = (float*)d_out + (size_t)B_ * HA_;

    float* ztT_p; cudaGetSymbolAddress((void**)&ztT_p, g_ztT);
    float* zqT_p; cudaGetSymbolAddress((void**)&zqT_p, g_zqT);

    dim3 blk(256);

    prep_kernel<<<1, 1>>>(logT);
    encodeT_kernel<<<dim3(F_ / BN, (N_ + BM - 1) / BM), blk>>>(train_obs, W_enc, ztT_p, N_, (size_t)NPAD);
    encodeT_kernel<<<dim3(F_ / BN, B_ / BM), blk>>>(query_obs, W_enc, zqT_p, B_, (size_t)B_);
    sim_kernel<<<dim3(NT_SIM, B_ / BM), blk>>>(zqT_p, ztT_p, query_indices, out_w);
    rowmax_kernel<<<B_, blk>>>();
    exp_kernel<<<dim3(NCH, B_), blk>>>(out_w);
    rowsum_kernel<<<(B_ + 255) / 256, blk>>>();
    pred_kernel<<<dim3(SPL, B_ / BM), blk>>>(train_actions, out_w);
    predsum_kernel<<<(B_ * HA_ + 255) / 256, blk>>>(out_pred);
}

// round 4
// speedup vs baseline: 1.6630x; 1.3061x over previous
#include <cuda_runtime.h>
#include <cuda_fp16.h>
#include <cstdint>

// ---------------- problem constants ----------------
#define B_   512
#define N_   100000
#define NPAD 100096    // N padded to multiple of 128
#define D_   256
#define F_   256
#define HA_  128

#define BM 128
#define BN 128
#define BK 16

#define NT_SIM (NPAD / 128)                // 782 column tiles
#define NCH    (((N_ / 4) + 255) / 256)    // 98
#define KC     1040
#define SPL    ((N_ + KC - 1) / KC)        // 97

// sim tiling
#define KCH   64                           // K halves per chunk (128B rows)
#define NCHK  (F_ / KCH)                   // 4 chunks
#define TILEB 16384                        // 128 rows * 64 halves * 2B
#define STAGEB (4 * TILEB)                 // Ah,Al,Bh,Bl
#define DYNSM (1024 + 2 * STAGEB)

// ---------------- device scratch ----------------
__device__ __half g_zt_hi[(size_t)NPAD * F_];
__device__ __half g_zt_lo[(size_t)NPAD * F_];
__device__ __half g_zq_hi[(size_t)B_ * F_];
__device__ __half g_zq_lo[(size_t)B_ * F_];
__device__ float  g_pmax[(size_t)B_ * NT_SIM];
__device__ float  g_rmax[B_];
__device__ float  g_psum[(size_t)B_ * NCH];
__device__ float  g_rinv[B_];
__device__ float  g_invT[1];
__device__ float  g_ppred[(size_t)SPL * B_ * HA_];

typedef unsigned long long ull;

// ---------------- f32x2 packed FMA ----------------
__device__ __forceinline__ ull pack2(float lo, float hi) {
    ull r; asm("mov.b64 %0, {%1,%2};" : "=l"(r) : "f"(lo), "f"(hi)); return r;
}
__device__ __forceinline__ float2 unpack2(ull v) {
    float2 f; asm("mov.b64 {%0,%1}, %2;" : "=f"(f.x), "=f"(f.y) : "l"(v)); return f;
}
__device__ __forceinline__ void fma2(ull& d, ull a, ull b) {
    asm("fma.rn.f32x2 %0, %1, %2, %0;" : "+l"(d) : "l"(a), "l"(b));
}

// ---------------- cp.async ----------------
__device__ __forceinline__ unsigned su(const void* p) {
    return (unsigned)__cvta_generic_to_shared(p);
}
__device__ __forceinline__ void cp16(unsigned d, const void* s) {
    asm volatile("cp.async.cg.shared.global [%0], [%1], 16;" :: "r"(d), "l"(s));
}
__device__ __forceinline__ void cpcommit() { asm volatile("cp.async.commit_group;"); }
__device__ __forceinline__ void cpwait0()  { asm volatile("cp.async.wait_group 0;"); }
__device__ __forceinline__ void cpwait1()  { asm volatile("cp.async.wait_group 1;"); }

// ---------------- ldmatrix / mma.sync (base ISA, no 'a' features) ----------------
#define LDSM4(r, addr) \
    asm volatile("ldmatrix.sync.aligned.m8n8.x4.shared.b16 {%0,%1,%2,%3}, [%4];" \
        : "=r"((r)[0]), "=r"((r)[1]), "=r"((r)[2]), "=r"((r)[3]) : "r"(addr))
#define LDSM2(r, addr) \
    asm volatile("ldmatrix.sync.aligned.m8n8.x2.shared.b16 {%0,%1}, [%2];" \
        : "=r"((r)[0]), "=r"((r)[1]) : "r"(addr))
#define MMA16816(d, a, b) \
    asm volatile("mma.sync.aligned.m16n8k16.row.col.f32.f16.f16.f32 " \
        "{%0,%1,%2,%3}, {%4,%5,%6,%7}, {%8,%9}, {%0,%1,%2,%3};" \
        : "+f"((d)[0]), "+f"((d)[1]), "+f"((d)[2]), "+f"((d)[3]) \
        : "r"((a)[0]), "r"((a)[1]), "r"((a)[2]), "r"((a)[3]), "r"((b)[0]), "r"((b)[1]))

// order-preserving float->uint key for atomicMax (exact max => deterministic)
__device__ __forceinline__ unsigned fkey(float f) {
    unsigned u = __float_as_uint(f);
    return (u & 0x80000000u) ? ~u : (u | 0x80000000u);
}
__device__ __forceinline__ float funkey(unsigned k) {
    return __uint_as_float((k & 0x80000000u) ? (k & 0x7FFFFFFFu) : ~k);
}

// ---------------- fast exp ----------------
__device__ __forceinline__ float fexp(float x)
{
    x = fmaxf(x, -87.0f);
    float t = x * 1.4426950408889634f;
    float n = rintf(t);
    float f = t - n;
    float p =            1.5403530393e-4f;
    p = fmaf(p, f, 1.3333558146e-3f);
    p = fmaf(p, f, 9.6181291076e-3f);
    p = fmaf(p, f, 5.5504108664e-2f);
    p = fmaf(p, f, 2.4022650696e-1f);
    p = fmaf(p, f, 6.9314718056e-1f);
    p = fmaf(p, f, 1.0f);
    int ni = (int)n;
    float s = __int_as_float((ni + 127) << 23);
    return p * s;
}

// ================= kernel 0: prep =================
__global__ void prep_kernel(const float* __restrict__ logT)
{
    g_invT[0] = expf(-logT[0]);
}

// ================= kernel 1: encode -> fp16 hi/lo (K-major) =================
__global__ __launch_bounds__(256, 2)
void encode_kernel(const float* __restrict__ A, const float* __restrict__ W,
                   __half* __restrict__ Hi, __half* __restrict__ Lo, int M)
{
    __shared__ __align__(16) float As[2][BK][BM + 4];
    __shared__ __align__(16) float Ws[2][BK][BN];
    const int tid = threadIdx.x, tx = tid & 15, ty = tid >> 4;
    const int rowBase = blockIdx.y * BM, colBase = blockIdx.x * BN;

    ull acc[8][4];
#pragma unroll
    for (int i = 0; i < 8; i++)
#pragma unroll
        for (int j = 0; j < 4; j++) acc[i][j] = 0ull;

    const int r4 = tid >> 2, c4 = (tid & 3) << 2;
    const int rw = tid >> 5, ow = (tid & 31) << 2;
    float4 pa[2];

    auto ldA = [&](int k0) {
#pragma unroll
        for (int l = 0; l < 2; l++) {
            int gr = rowBase + r4 + l * 64;
            pa[l] = make_float4(0.f, 0.f, 0.f, 0.f);
            if (gr < M) pa[l] = *(const float4*)(A + (size_t)gr * D_ + k0 + c4);
        }
    };
    auto stsA = [&](int buf) {
#pragma unroll
        for (int l = 0; l < 2; l++) {
            int r = r4 + l * 64;
            As[buf][c4 + 0][r] = pa[l].x; As[buf][c4 + 1][r] = pa[l].y;
            As[buf][c4 + 2][r] = pa[l].z; As[buf][c4 + 3][r] = pa[l].w;
        }
    };
    auto cpW = [&](int buf, int k0) {
#pragma unroll
        for (int l = 0; l < 2; l++)
            cp16(su(&Ws[buf][rw + l * 8][ow]),
                 W + (size_t)(k0 + rw + l * 8) * F_ + colBase + ow);
        cpcommit();
    };

    ldA(0); cpW(0, 0);
    stsA(0); cpwait0(); __syncthreads();

#pragma unroll 2
    for (int it = 0; it < D_ / BK; it++) {
        const int cur = it & 1;
        if (it + 1 < D_ / BK) { ldA((it + 1) * BK); cpW(cur ^ 1, (it + 1) * BK); }
#pragma unroll
        for (int k = 0; k < BK; k++) {
            float4 a0 = *(const float4*)&As[cur][k][ty * 8];
            float4 a1 = *(const float4*)&As[cur][k][ty * 8 + 4];
            ulonglong2 b0 = *(const ulonglong2*)&Ws[cur][k][tx * 8];
            ulonglong2 b1 = *(const ulonglong2*)&Ws[cur][k][tx * 8 + 4];
            float av[8] = {a0.x, a0.y, a0.z, a0.w, a1.x, a1.y, a1.z, a1.w};
#pragma unroll
            for (int i = 0; i < 8; i++) {
                ull ap = pack2(av[i], av[i]);
                fma2(acc[i][0], ap, b0.x); fma2(acc[i][1], ap, b0.y);
                fma2(acc[i][2], ap, b1.x); fma2(acc[i][3], ap, b1.y);
            }
        }
        if (it + 1 < D_ / BK) { stsA(cur ^ 1); cpwait0(); }
        __syncthreads();
    }

#pragma unroll
    for (int i = 0; i < 8; i++) {
        float cr[8];
#pragma unroll
        for (int j2 = 0; j2 < 4; j2++) {
            float2 u = unpack2(acc[i][j2]);
            cr[2 * j2] = u.x; cr[2 * j2 + 1] = u.y;
        }
        __align__(16) __half h[8], l[8];
#pragma unroll
        for (int j = 0; j < 8; j++) {
            h[j] = __float2half_rn(cr[j]);
            l[j] = __float2half_rn(cr[j] - __half2float(h[j]));
        }
        const size_t m = (size_t)(rowBase + ty * 8 + i);
        const size_t f0 = (size_t)(colBase + tx * 8);
        *(uint4*)(Hi + m * F_ + f0) = *(const uint4*)h;
        *(uint4*)(Lo + m * F_ + f0) = *(const uint4*)l;
    }
}

// ================= kernel 2: sim via mma.sync (fp16-split, 3 products) =================
// CTA: 128 query rows x 128 train cols. 8 warps in 2x4 grid, warp tile 64x32.
__global__ __launch_bounds__(256, 1)
void sim_kernel(const __half* __restrict__ QH, const __half* __restrict__ QL,
                const __half* __restrict__ TH, const __half* __restrict__ TL,
                const long long* __restrict__ qidx, float* __restrict__ Wout)
{
    extern __shared__ __align__(16) char dsm_raw[];
    __shared__ int      s_q[BM];
    __shared__ unsigned s_red[BM];

    const uint32_t dynBase = (su(dsm_raw) + 1023u) & ~1023u;
    const int tid = threadIdx.x, wid = tid >> 5, t = tid & 31;
    const int warpM = wid >> 2, warpN = wid & 3;
    const int rowBase = blockIdx.y * BM;
    const int colBase = blockIdx.x * BN;

    if (tid < BM) { s_q[tid] = (int)qidx[rowBase + tid]; s_red[tid] = 0u; }

    // stage load: 4 tiles (Ah, Al, Bh, Bl), each 128 rows x 64 halves, swizzled 128B rows
    const __half* srcs[4] = { QH + (size_t)rowBase * F_, QL + (size_t)rowBase * F_,
                              TH + (size_t)colBase * F_, TL + (size_t)colBase * F_ };
    auto loadStage = [&](int st, int ck) {
        const int k0 = ck * KCH;
        const uint32_t sb = dynBase + st * STAGEB;
#pragma unroll
        for (int tt = 0; tt < 4; tt++) {
            const __half* s = srcs[tt] + k0;
#pragma unroll
            for (int i = 0; i < 4; i++) {
                int lin = tid + i * 256;
                int row = lin >> 3, c16 = lin & 7;
                uint32_t off = (uint32_t)(row * 128 + c16 * 16);
                cp16(sb + tt * TILEB + (off ^ ((row & 7) * 16)),
                     s + (size_t)row * F_ + c16 * 8);
            }
        }
        cpcommit();
    };

    // fragment address bases (un-swizzled); xorv applied at use
    const uint32_t xorv = (uint32_t)((t & 7) * 16);
    uint32_t aOff[4], bOff[4];
#pragma unroll
    for (int mt = 0; mt < 4; mt++) {
        int row = warpM * 64 + mt * 16 + (t & 15);
        aOff[mt] = (uint32_t)(row * 128 + (t >> 4) * 16);
    }
#pragma unroll
    for (int nt = 0; nt < 4; nt++) {
        int row = warpN * 32 + nt * 8 + (t & 7);
        bOff[nt] = (uint32_t)(row * 128 + ((t >> 3) & 1) * 16);
    }

    float acc[4][4][4];
#pragma unroll
    for (int mt = 0; mt < 4; mt++)
#pragma unroll
        for (int nt = 0; nt < 4; nt++)
#pragma unroll
            for (int j = 0; j < 4; j++) acc[mt][nt][j] = 0.f;

    loadStage(0, 0);
    loadStage(1, 1);

    for (int s = 0; s < NCHK; s++) {
        const int b = s & 1;
        if (s < 3) cpwait1(); else cpwait0();
        __syncthreads();
        const uint32_t sb = dynBase + b * STAGEB;
#pragma unroll
        for (int k16 = 0; k16 < 4; k16++) {
            uint32_t ah[4][4], al[4][4], bh[4][2], bl[4][2];
#pragma unroll
            for (int mt = 0; mt < 4; mt++) {
                uint32_t o = (aOff[mt] + k16 * 32) ^ xorv;
                LDSM4(ah[mt], sb + o);
                LDSM4(al[mt], sb + TILEB + o);
            }
#pragma unroll
            for (int nt = 0; nt < 4; nt++) {
                uint32_t o = (bOff[nt] + k16 * 32) ^ xorv;
                LDSM2(bh[nt], sb + 2 * TILEB + o);
                LDSM2(bl[nt], sb + 3 * TILEB + o);
            }
#pragma unroll
            for (int mt = 0; mt < 4; mt++)
#pragma unroll
                for (int nt = 0; nt < 4; nt++) {
                    MMA16816(acc[mt][nt], ah[mt], bh[nt]);
                    MMA16816(acc[mt][nt], ah[mt], bl[nt]);
                    MMA16816(acc[mt][nt], al[mt], bh[nt]);
                }
        }
        __syncthreads();
        if (s < 2) loadStage(b, s + 2);
    }

    // epilogue: exclusion + store + row-max
    const int qr = t >> 2, qc = (t & 3) * 2;
#pragma unroll
    for (int mt = 0; mt < 4; mt++) {
#pragma unroll
        for (int h = 0; h < 2; h++) {
            const int lr = warpM * 64 + mt * 16 + qr + h * 8;
            const int gr = rowBase + lr;
            const int qi = s_q[lr];
            float* orow = Wout + (size_t)gr * N_;
            float lm = -3.0e38f;
#pragma unroll
            for (int nt = 0; nt < 4; nt++) {
                int gc = colBase + warpN * 32 + nt * 8 + qc;
                if (gc < N_) {
                    float x = acc[mt][nt][h * 2 + 0];
                    float y = acc[mt][nt][h * 2 + 1];
                    if (gc == qi)     x = -1e9f;
                    if (gc + 1 == qi) y = -1e9f;
                    *(float2*)(orow + gc) = make_float2(x, y);
                    lm = fmaxf(lm, fmaxf(x, y));
                }
            }
            atomicMax(&s_red[lr], fkey(lm));
        }
    }
    __syncthreads();
    if (tid < BM)
        g_pmax[(size_t)(rowBase + tid) * NT_SIM + blockIdx.x] = funkey(s_red[tid]);
}

// ================= kernel 3: per-row max =================
__global__ __launch_bounds__(256)
void rowmax_kernel()
{
    const int row = blockIdx.x;
    const int tid = threadIdx.x;
    float m = -3.0e38f;
    for (int t = tid; t < NT_SIM; t += 256)
        m = fmaxf(m, g_pmax[(size_t)row * NT_SIM + t]);
    __shared__ float sm[256];
    sm[tid] = m; __syncthreads();
    for (int s = 128; s > 0; s >>= 1) {
        if (tid < s) sm[tid] = fmaxf(sm[tid], sm[tid + s]);
        __syncthreads();
    }
    if (tid == 0) g_rmax[row] = sm[0];
}

// ================= kernel 4: exp pass (in place) + chunk sums =================
__global__ __launch_bounds__(256)
void exp_kernel(float* __restrict__ Wbuf)
{
    const int row = blockIdx.y;
    const int tid = threadIdx.x;
    const float invT = g_invT[0];
    const float m = g_rmax[row];
    const int i4 = blockIdx.x * 256 + tid;
    float ls = 0.f;
    if (i4 < N_ / 4) {
        float4 v = *(float4*)(Wbuf + (size_t)row * N_ + (size_t)i4 * 4);
        v.x = fexp((v.x - m) * invT);
        v.y = fexp((v.y - m) * invT);
        v.z = fexp((v.z - m) * invT);
        v.w = fexp((v.w - m) * invT);
        *(float4*)(Wbuf + (size_t)row * N_ + (size_t)i4 * 4) = v;
        ls = (v.x + v.y) + (v.z + v.w);
    }
    __shared__ float sm[256];
    sm[tid] = ls; __syncthreads();
    for (int s = 128; s > 0; s >>= 1) {
        if (tid < s) sm[tid] += sm[tid + s];
        __syncthreads();
    }
    if (tid == 0) g_psum[(size_t)row * NCH + blockIdx.x] = sm[0];
}

// ================= kernel 5: per-row 1/sum =================
__global__ __launch_bounds__(256)
void rowsum_kernel()
{
    const int row = blockIdx.x * 256 + threadIdx.x;
    if (row < B_) {
        float s = 0.f;
        for (int c = 0; c < NCH; c++) s += g_psum[(size_t)row * NCH + c];
        g_rinv[row] = 1.f / s;
    }
}

// ===== kernel 6: split-K pred GEMM; normalizes + writes final weights en route =====
__global__ __launch_bounds__(256, 2)
void pred_kernel(const float* __restrict__ Act, float* __restrict__ Wbuf)
{
    __shared__ __align__(16) float Ws[2][BK][BM + 4];
    __shared__ __align__(16) float Bs[2][BK][HA_];
    __shared__ float s_inv[BM];
    const int tid = threadIdx.x, tx = tid & 15, ty = tid >> 4;
    const int rowBase = blockIdx.y * BM;
    const int kBase = blockIdx.x * KC;
    const int nIt = (min(kBase + KC, N_) - kBase) / BK;
    if (tid < BM) s_inv[tid] = g_rinv[rowBase + tid];

    const int r4 = tid >> 2, c4 = (tid & 3) << 2;
    const int rw = tid >> 5, ow = (tid & 31) << 2;
    float4 pw[2];

    auto ldW = [&](int k0) {
#pragma unroll
        for (int l = 0; l < 2; l++) {
            int r = r4 + l * 64;
            pw[l] = *(const float4*)(Wbuf + (size_t)(rowBase + r) * N_ + k0 + c4);
        }
    };
    auto stsW = [&](int buf, int k0) {
#pragma unroll
        for (int l = 0; l < 2; l++) {
            int r = r4 + l * 64;
            float inv = s_inv[r];
            float4 v = pw[l];
            v.x *= inv; v.y *= inv; v.z *= inv; v.w *= inv;
            *(float4*)(Wbuf + (size_t)(rowBase + r) * N_ + k0 + c4) = v;
            Ws[buf][c4 + 0][r] = v.x; Ws[buf][c4 + 1][r] = v.y;
            Ws[buf][c4 + 2][r] = v.z; Ws[buf][c4 + 3][r] = v.w;
        }
    };
    auto cpB = [&](int buf, int k0) {
#pragma unroll
        for (int l = 0; l < 2; l++) {
            int r = rw + 8 * l;
            cp16(su(&Bs[buf][r][ow]), Act + (size_t)(k0 + r) * HA_ + ow);
        }
        cpcommit();
    };

    ull acc[8][4];
#pragma unroll
    for (int i = 0; i < 8; i++)
#pragma unroll
        for (int j = 0; j < 4; j++) acc[i][j] = 0ull;

    ldW(kBase); cpB(0, kBase);
    __syncthreads();
    stsW(0, kBase); cpwait0(); __syncthreads();

    for (int it = 0; it < nIt; it++) {
        const int cur = it & 1;
        const int k1 = kBase + (it + 1) * BK;
        if (it + 1 < nIt) { ldW(k1); cpB(cur ^ 1, k1); }
#pragma unroll
        for (int k = 0; k < BK; k++) {
            float4 a0 = *(const float4*)&Ws[cur][k][ty * 8];
            float4 a1 = *(const float4*)&Ws[cur][k][ty * 8 + 4];
            ulonglong2 b0 = *(const ulonglong2*)&Bs[cur][k][tx * 8];
            ulonglong2 b1 = *(const ulonglong2*)&Bs[cur][k][tx * 8 + 4];
            float av[8] = {a0.x, a0.y, a0.z, a0.w, a1.x, a1.y, a1.z, a1.w};
#pragma unroll
            for (int i = 0; i < 8; i++) {
                ull ap = pack2(av[i], av[i]);
                fma2(acc[i][0], ap, b0.x); fma2(acc[i][1], ap, b0.y);
                fma2(acc[i][2], ap, b1.x); fma2(acc[i][3], ap, b1.y);
            }
        }
        if (it + 1 < nIt) { stsW(cur ^ 1, k1); cpwait0(); }
        __syncthreads();
    }

    float* pp = g_ppred + (size_t)blockIdx.x * (B_ * HA_);
#pragma unroll
    for (int i = 0; i < 8; i++) {
        int row = rowBase + ty * 8 + i;
        float2 u0 = unpack2(acc[i][0]), u1 = unpack2(acc[i][1]);
        float2 u2 = unpack2(acc[i][2]), u3 = unpack2(acc[i][3]);
        float* cp = pp + (size_t)row * HA_ + tx * 8;
        *(float4*)cp       = make_float4(u0.x, u0.y, u1.x, u1.y);
        *(float4*)(cp + 4) = make_float4(u2.x, u2.y, u3.x, u3.y);
    }
}

// ================= kernel 7: split-K reduction =================
__global__ __launch_bounds__(256)
void predsum_kernel(float* __restrict__ outPred)
{
    const int idx = blockIdx.x * 256 + threadIdx.x;
    if (idx < B_ * HA_) {
        float s = 0.f;
        for (int t = 0; t < SPL; t++)
            s += g_ppred[(size_t)t * (B_ * HA_) + idx];
        outPred[idx] = s;
    }
}

// ================= launch =================
extern "C" void kernel_launch(void* const* d_in, const int* in_sizes, int n_in,
                              void* d_out, int out_size)
{
    const float*     query_obs     = (const float*)d_in[0];
    const long long* query_indices = (const long long*)d_in[1];
    const float*     W_enc         = (const float*)d_in[2];
    const float*     train_obs     = (const float*)d_in[3];
    const float*     train_actions = (const float*)d_in[4];
    const float*     logT          = (const float*)d_in[5];

    float* out_pred = (float*)d_out;
    float* out_w    = (float*)d_out + (size_t)B_ * HA_;

    __half *zth, *ztl, *zqh, *zql;
    cudaGetSymbolAddress((void**)&zth, g_zt_hi);
    cudaGetSymbolAddress((void**)&ztl, g_zt_lo);
    cudaGetSymbolAddress((void**)&zqh, g_zq_hi);
    cudaGetSymbolAddress((void**)&zql, g_zq_lo);

    cudaFuncSetAttribute(sim_kernel, cudaFuncAttributeMaxDynamicSharedMemorySize, DYNSM);

    dim3 blk(256);
    prep_kernel<<<1, 1>>>(logT);
    encode_kernel<<<dim3(F_ / BN, NPAD / BM), blk>>>(train_obs, W_enc, zth, ztl, N_);
    encode_kernel<<<dim3(F_ / BN, B_ / BM), blk>>>(query_obs, W_enc, zqh, zql, B_);
    sim_kernel<<<dim3(NT_SIM, B_ / BM), blk, DYNSM>>>(zqh, zql, zth, ztl, query_indices, out_w);
    rowmax_kernel<<<B_, blk>>>();
    exp_kernel<<<dim3(NCH, B_), blk>>>(out_w);
    rowsum_kernel<<<(B_ + 255) / 256, blk>>>();
    pred_kernel<<<dim3(SPL, B_ / BM), blk>>>(train_actions, out_w);
    predsum_kernel<<<(B_ * HA_ + 255) / 256, blk>>>(out_pred);
}

// round 7
// speedup vs baseline: 2.3987x; 1.4424x over previous
#include <cuda_runtime.h>
#include <cuda_fp16.h>
#include <cstdint>

// ---------------- problem constants ----------------
#define B_   512
#define N_   100000
#define NPAD 100096    // N padded to multiple of 128
#define D_   256
#define F_   256
#define HA_  128

#define BM 128

#define NT_SIM (NPAD / 128)                // 782 column tiles
#define NCH    (((NPAD / 4) + 255) / 256)  // 98 chunks (covers pad)
#define KC2    1024                        // pred split-K chunk
#define SPL2   ((NPAD + KC2 - 1) / KC2)    // 98 splits

// mma staging geometry (all three GEMM kernels)
#define KCH   64                           // K halves per stage (128B rows)
#define TILEB 16384                        // 128 rows * 64 halves * 2B
#define STAGEB (4 * TILEB)                 // 4 tiles per stage
#define DYNSM (1024 + 2 * STAGEB)          // align pad + 2 stages

// ---------------- device scratch ----------------
__device__ __align__(16) __half g_zt_hi[(size_t)NPAD * F_];
__device__ __align__(16) __half g_zt_lo[(size_t)NPAD * F_];
__device__ __align__(16) __half g_zq_hi[(size_t)B_ * F_];
__device__ __align__(16) __half g_zq_lo[(size_t)B_ * F_];
__device__ __align__(16) __half g_wt_hi[(size_t)F_ * D_];   // W^T split
__device__ __align__(16) __half g_wt_lo[(size_t)F_ * D_];
__device__ __align__(16) __half g_e_hi[(size_t)B_ * NPAD];  // exp(e) pairs
__device__ __align__(16) __half g_e_lo[(size_t)B_ * NPAD];
__device__ __align__(16) __half g_aT_hi[(size_t)HA_ * NPAD];// actions^T split
__device__ __align__(16) __half g_aT_lo[(size_t)HA_ * NPAD];
__device__ float  g_pmax[(size_t)B_ * NT_SIM];
__device__ float  g_rmax[B_];
__device__ float  g_psum[(size_t)B_ * NCH];
__device__ float  g_rinv[B_];
__device__ float  g_invT[1];
__device__ float  g_ppred[(size_t)SPL2 * B_ * HA_];

// ---------------- helpers ----------------
__device__ __forceinline__ unsigned su(const void* p) {
    return (unsigned)__cvta_generic_to_shared(p);
}
__device__ __forceinline__ void cp16(unsigned d, const void* s) {
    asm volatile("cp.async.cg.shared.global [%0], [%1], 16;" :: "r"(d), "l"(s));
}
__device__ __forceinline__ void cpcommit() { asm volatile("cp.async.commit_group;"); }
__device__ __forceinline__ void cpwait0()  { asm volatile("cp.async.wait_group 0;"); }
__device__ __forceinline__ void cpwait1()  { asm volatile("cp.async.wait_group 1;"); }

#define LDSM4(r, addr) \
    asm volatile("ldmatrix.sync.aligned.m8n8.x4.shared.b16 {%0,%1,%2,%3}, [%4];" \
        : "=r"((r)[0]), "=r"((r)[1]), "=r"((r)[2]), "=r"((r)[3]) : "r"(addr))
#define LDSM2(r, addr) \
    asm volatile("ldmatrix.sync.aligned.m8n8.x2.shared.b16 {%0,%1}, [%2];" \
        : "=r"((r)[0]), "=r"((r)[1]) : "r"(addr))
#define MMA16816(d, a, b) \
    asm volatile("mma.sync.aligned.m16n8k16.row.col.f32.f16.f16.f32 " \
        "{%0,%1,%2,%3}, {%4,%5,%6,%7}, {%8,%9}, {%0,%1,%2,%3};" \
        : "+f"((d)[0]), "+f"((d)[1]), "+f"((d)[2]), "+f"((d)[3]) \
        : "r"((a)[0]), "r"((a)[1]), "r"((a)[2]), "r"((a)[3]), "r"((b)[0]), "r"((b)[1]))

__device__ __forceinline__ unsigned fkey(float f) {
    unsigned u = __float_as_uint(f);
    return (u & 0x80000000u) ? ~u : (u | 0x80000000u);
}
__device__ __forceinline__ float funkey(unsigned k) {
    return __uint_as_float((k & 0x80000000u) ? (k & 0x7FFFFFFFu) : ~k);
}
__device__ __forceinline__ uint32_t pkh(__half a, __half b) {
    __half2 h = __halves2half2(a, b);
    return *(uint32_t*)&h;
}

__device__ __forceinline__ float fexp(float x)
{
    x = fmaxf(x, -87.0f);
    float t = x * 1.4426950408889634f;
    float n = rintf(t);
    float f = t - n;
    float p =            1.5403530393e-4f;
    p = fmaf(p, f, 1.3333558146e-3f);
    p = fmaf(p, f, 9.6181291076e-3f);
    p = fmaf(p, f, 5.5504108664e-2f);
    p = fmaf(p, f, 2.4022650696e-1f);
    p = fmaf(p, f, 6.9314718056e-1f);
    p = fmaf(p, f, 1.0f);
    int ni = (int)n;
    float s = __int_as_float((ni + 127) << 23);
    return p * s;
}

// ================= kernel: prep (invT) =================
__global__ void prep_kernel(const float* __restrict__ logT)
{
    g_invT[0] = expf(-logT[0]);
}

// ================= kernel: W_enc transpose + fp16 split =================
__global__ void wsplit_kernel(const float* __restrict__ W)
{
    __shared__ float s[32][33];
    const int k0 = blockIdx.x * 32, f0 = blockIdx.y * 32;
    const int tx = threadIdx.x, ty = threadIdx.y;
#pragma unroll
    for (int l = 0; l < 4; l++)
        s[ty + l * 8][tx] = W[(size_t)(k0 + ty + l * 8) * F_ + f0 + tx];
    __syncthreads();
#pragma unroll
    for (int l = 0; l < 4; l++) {
        float v = s[tx][ty + l * 8];
        __half h = __float2half_rn(v);
        __half lo = __float2half_rn(v - __half2float(h));
        g_wt_hi[(size_t)(f0 + ty + l * 8) * D_ + k0 + tx] = h;
        g_wt_lo[(size_t)(f0 + ty + l * 8) * D_ + k0 + tx] = lo;
    }
}

// ================= kernel: actions transpose + fp16 split =================
__global__ void atsplit_kernel(const float* __restrict__ Act)
{
    __shared__ float s[32][33];
    const int n0 = blockIdx.x * 32, j0 = blockIdx.y * 32;
    const int tx = threadIdx.x, ty = threadIdx.y;
#pragma unroll
    for (int l = 0; l < 4; l++) {
        int n = n0 + ty + l * 8;
        float v = 0.f;
        if (n < N_) v = Act[(size_t)n * HA_ + j0 + tx];
        s[ty + l * 8][tx] = v;
    }
    __syncthreads();
#pragma unroll
    for (int l = 0; l < 4; l++) {
        int j = j0 + ty + l * 8;
        float v = s[tx][ty + l * 8];
        __half h = __float2half_rn(v);
        __half lo = __float2half_rn(v - __half2float(h));
        g_aT_hi[(size_t)j * NPAD + n0 + tx] = h;
        g_aT_lo[(size_t)j * NPAD + n0 + tx] = lo;
    }
}

// ================= kernel: encode via mma.sync (fp16-split, 3 products) =================
// Z[m][f] = sum_k A[m][k] W[k][f];  A fp32 split inline, B = WT planes.
__global__ __launch_bounds__(256, 1)
void encode_kernel(const float* __restrict__ A,
                   __half* __restrict__ Zh, __half* __restrict__ Zl, int M)
{
    extern __shared__ __align__(16) char dsm_raw[];
    char* dynPtr = (char*)(((uintptr_t)dsm_raw + 1023) & ~(uintptr_t)1023);
    const uint32_t dynBase = su(dynPtr);
    const int tid = threadIdx.x, wid = tid >> 5, t = tid & 31;
    const int warpM = wid >> 2, warpN = wid & 3;
    const int rowBase = blockIdx.y * BM;
    const int colBase = blockIdx.x * 128;

    float4 pa[8];
    auto ldA = [&](int k0) {
#pragma unroll
        for (int i = 0; i < 8; i++) {
            int lin = tid + i * 256;
            int row = lin >> 4;
            int c4 = (lin & 15) << 2;
            int gr = rowBase + row;
            pa[i] = make_float4(0.f, 0.f, 0.f, 0.f);
            if (gr < M) pa[i] = *(const float4*)(A + (size_t)gr * D_ + k0 + c4);
        }
    };
    auto stsA = [&](int st) {
        char* sb = dynPtr + st * STAGEB;
#pragma unroll
        for (int i = 0; i < 8; i++) {
            int lin = tid + i * 256;
            int row = lin >> 4;
            int c4 = (lin & 15) << 2;
            uint32_t off = (uint32_t)(row * 128 + c4 * 2) ^ (uint32_t)((row & 7) * 16);
            float v[4] = {pa[i].x, pa[i].y, pa[i].z, pa[i].w};
            __half h[4], l[4];
#pragma unroll
            for (int j = 0; j < 4; j++) {
                h[j] = __float2half_rn(v[j]);
                l[j] = __float2half_rn(v[j] - __half2float(h[j]));
            }
            uint2 uh = make_uint2(pkh(h[0], h[1]), pkh(h[2], h[3]));
            uint2 ul = make_uint2(pkh(l[0], l[1]), pkh(l[2], l[3]));
            *(uint2*)(sb + off) = uh;
            *(uint2*)(sb + TILEB + off) = ul;
        }
    };
    auto cpB = [&](int st, int k0) {
        const uint32_t sb = dynBase + st * STAGEB;
#pragma unroll
        for (int i = 0; i < 4; i++) {
            int lin = tid + i * 256;
            int row = lin >> 3, c16 = lin & 7;
            uint32_t off = (uint32_t)(row * 128 + c16 * 16) ^ (uint32_t)((row & 7) * 16);
            cp16(sb + 2 * TILEB + off, g_wt_hi + (size_t)(colBase + row) * D_ + k0 + c16 * 8);
            cp16(sb + 3 * TILEB + off, g_wt_lo + (size_t)(colBase + row) * D_ + k0 + c16 * 8);
        }
        cpcommit();
    };

    const uint32_t xorv = (uint32_t)((t & 7) * 16);
    uint32_t aOff[4], bOff[4];
#pragma unroll
    for (int mt = 0; mt < 4; mt++) {
        int row = warpM * 64 + mt * 16 + (t & 15);
        aOff[mt] = (uint32_t)(row * 128 + (t >> 4) * 16);
    }
#pragma unroll
    for (int nt = 0; nt < 4; nt++) {
        int row = warpN * 32 + nt * 8 + (t & 7);
        bOff[nt] = (uint32_t)(row * 128 + ((t >> 3) & 1) * 16);
    }

    float acc[4][4][4];
#pragma unroll
    for (int mt = 0; mt < 4; mt++)
#pragma unroll
        for (int nt = 0; nt < 4; nt++)
#pragma unroll
            for (int j = 0; j < 4; j++) acc[mt][nt][j] = 0.f;

    ldA(0); cpB(0, 0);
    stsA(0); cpwait0(); __syncthreads();

    for (int it = 0; it < 4; it++) {
        const int cur = it & 1;
        if (it < 3) { ldA((it + 1) * KCH); cpB(cur ^ 1, (it + 1) * KCH); }
        const uint32_t sb = dynBase + cur * STAGEB;
#pragma unroll
        for (int k16 = 0; k16 < 4; k16++) {
            uint32_t ah[4][4], al[4][4], bh[4][2], bl[4][2];
#pragma unroll
            for (int mt = 0; mt < 4; mt++) {
                uint32_t o = (aOff[mt] + k16 * 32) ^ xorv;
                LDSM4(ah[mt], sb + o);
                LDSM4(al[mt], sb + TILEB + o);
            }
#pragma unroll
            for (int nt = 0; nt < 4; nt++) {
                uint32_t o = (bOff[nt] + k16 * 32) ^ xorv;
                LDSM2(bh[nt], sb + 2 * TILEB + o);
                LDSM2(bl[nt], sb + 3 * TILEB + o);
            }
#pragma unroll
            for (int mt = 0; mt < 4; mt++)
#pragma unroll
                for (int nt = 0; nt < 4; nt++) {
                    MMA16816(acc[mt][nt], ah[mt], bh[nt]);
                    MMA16816(acc[mt][nt], ah[mt], bl[nt]);
                    MMA16816(acc[mt][nt], al[mt], bh[nt]);
                }
        }
        if (it < 3) { stsA(cur ^ 1); cpwait0(); }
        __syncthreads();
    }

    // epilogue: fp32 acc -> fp16 hi/lo pair stores
    const int qr = t >> 2, qc = (t & 3) * 2;
#pragma unroll
    for (int mt = 0; mt < 4; mt++)
#pragma unroll
        for (int h = 0; h < 2; h++) {
            const size_t m = (size_t)(rowBase + warpM * 64 + mt * 16 + qr + h * 8);
#pragma unroll
            for (int nt = 0; nt < 4; nt++) {
                const int gc = colBase + warpN * 32 + nt * 8 + qc;
                float x = acc[mt][nt][h * 2 + 0];
                float y = acc[mt][nt][h * 2 + 1];
                __half hx = __float2half_rn(x), hy = __float2half_rn(y);
                __half lx = __float2half_rn(x - __half2float(hx));
                __half ly = __float2half_rn(y - __half2float(hy));
                *(__half2*)(Zh + m * F_ + gc) = __halves2half2(hx, hy);
                *(__half2*)(Zl + m * F_ + gc) = __halves2half2(lx, ly);
            }
        }
}

// ================= kernel: sim via mma.sync =================
__global__ __launch_bounds__(256, 1)
void sim_kernel(const long long* __restrict__ qidx, float* __restrict__ Wout)
{
    extern __shared__ __align__(16) char dsm_raw[];
    __shared__ int      s_q[BM];
    __shared__ unsigned s_red[BM];

    char* dynPtr = (char*)(((uintptr_t)dsm_raw + 1023) & ~(uintptr_t)1023);
    const uint32_t dynBase = su(dynPtr);
    const int tid = threadIdx.x, wid = tid >> 5, t = tid & 31;
    const int warpM = wid >> 2, warpN = wid & 3;
    const int rowBase = blockIdx.y * BM;
    const int colBase = blockIdx.x * 128;

    if (tid < BM) { s_q[tid] = (int)qidx[rowBase + tid]; s_red[tid] = 0u; }

    const __half* srcs[4] = { g_zq_hi + (size_t)rowBase * F_, g_zq_lo + (size_t)rowBase * F_,
                              g_zt_hi + (size_t)colBase * F_, g_zt_lo + (size_t)colBase * F_ };
    auto loadStage = [&](int st, int ck) {
        const int k0 = ck * KCH;
        const uint32_t sb = dynBase + st * STAGEB;
#pragma unroll
        for (int tt = 0; tt < 4; tt++) {
            const __half* s = srcs[tt] + k0;
#pragma unroll
            for (int i = 0; i < 4; i++) {
                int lin = tid + i * 256;
                int row = lin >> 3, c16 = lin & 7;
                uint32_t off = (uint32_t)(row * 128 + c16 * 16);
                cp16(sb + tt * TILEB + (off ^ ((row & 7) * 16)),
                     s + (size_t)row * F_ + c16 * 8);
            }
        }
        cpcommit();
    };

    const uint32_t xorv = (uint32_t)((t & 7) * 16);
    uint32_t aOff[4], bOff[4];
#pragma unroll
    for (int mt = 0; mt < 4; mt++) {
        int row = warpM * 64 + mt * 16 + (t & 15);
        aOff[mt] = (uint32_t)(row * 128 + (t >> 4) * 16);
    }
#pragma unroll
    for (int nt = 0; nt < 4; nt++) {
        int row = warpN * 32 + nt * 8 + (t & 7);
        bOff[nt] = (uint32_t)(row * 128 + ((t >> 3) & 1) * 16);
    }

    float acc[4][4][4];
#pragma unroll
    for (int mt = 0; mt < 4; mt++)
#pragma unroll
        for (int nt = 0; nt < 4; nt++)
#pragma unroll
            for (int j = 0; j < 4; j++) acc[mt][nt][j] = 0.f;

    loadStage(0, 0);
    loadStage(1, 1);

    for (int s = 0; s < 4; s++) {
        const int b = s & 1;
        if (s < 3) cpwait1(); else cpwait0();
        __syncthreads();
        const uint32_t sb = dynBase + b * STAGEB;
#pragma unroll
        for (int k16 = 0; k16 < 4; k16++) {
            uint32_t ah[4][4], al[4][4], bh[4][2], bl[4][2];
#pragma unroll
            for (int mt = 0; mt < 4; mt++) {
                uint32_t o = (aOff[mt] + k16 * 32) ^ xorv;
                LDSM4(ah[mt], sb + o);
                LDSM4(al[mt], sb + TILEB + o);
            }
#pragma unroll
            for (int nt = 0; nt < 4; nt++) {
                uint32_t o = (bOff[nt] + k16 * 32) ^ xorv;
                LDSM2(bh[nt], sb + 2 * TILEB + o);
                LDSM2(bl[nt], sb + 3 * TILEB + o);
            }
#pragma unroll
            for (int mt = 0; mt < 4; mt++)
#pragma unroll
                for (int nt = 0; nt < 4; nt++) {
                    MMA16816(acc[mt][nt], ah[mt], bh[nt]);
                    MMA16816(acc[mt][nt], ah[mt], bl[nt]);
                    MMA16816(acc[mt][nt], al[mt], bh[nt]);
                }
        }
        __syncthreads();
        if (s < 2) loadStage(b, s + 2);
    }

    const int qr = t >> 2, qc = (t & 3) * 2;
#pragma unroll
    for (int mt = 0; mt < 4; mt++) {
#pragma unroll
        for (int h = 0; h < 2; h++) {
            const int lr = warpM * 64 + mt * 16 + qr + h * 8;
            const int gr = rowBase + lr;
            const int qi = s_q[lr];
            float* orow = Wout + (size_t)gr * N_;
            float lm = -3.0e38f;
#pragma unroll
            for (int nt = 0; nt < 4; nt++) {
                int gc = colBase + warpN * 32 + nt * 8 + qc;
                if (gc < N_) {
                    float x = acc[mt][nt][h * 2 + 0];
                    float y = acc[mt][nt][h * 2 + 1];
                    if (gc == qi)     x = -1e9f;
                    if (gc + 1 == qi) y = -1e9f;
                    *(float2*)(orow + gc) = make_float2(x, y);
                    lm = fmaxf(lm, fmaxf(x, y));
                }
            }
            atomicMax(&s_red[lr], fkey(lm));
        }
    }
    __syncthreads();
    if (tid < BM)
        g_pmax[(size_t)(rowBase + tid) * NT_SIM + blockIdx.x] = funkey(s_red[tid]);
}

// ================= kernel: per-row max =================
__global__ __launch_bounds__(256)
void rowmax_kernel()
{
    const int row = blockIdx.x;
    const int tid = threadIdx.x;
    float m = -3.0e38f;
    for (int t = tid; t < NT_SIM; t += 256)
        m = fmaxf(m, g_pmax[(size_t)row * NT_SIM + t]);
    __shared__ float sm[256];
    sm[tid] = m; __syncthreads();
    for (int s = 128; s > 0; s >>= 1) {
        if (tid < s) sm[tid] = fmaxf(sm[tid], sm[tid + s]);
        __syncthreads();
    }
    if (tid == 0) g_rmax[row] = sm[0];
}

// ================= kernel: exp -> fp16 hi/lo planes + chunk sums =================
__global__ __launch_bounds__(256)
void exp_kernel(const float* __restrict__ Sim)
{
    const int row = blockIdx.y;
    const int tid = threadIdx.x;
    const float invT = g_invT[0];
    const float m = g_rmax[row];
    const int i4 = blockIdx.x * 256 + tid;
    float ls = 0.f;
    if (i4 < NPAD / 4) {
        const int gc = i4 * 4;
        uint2 uh = make_uint2(0u, 0u), ul = make_uint2(0u, 0u);
        if (gc < N_) {
            float4 v = *(const float4*)(Sim + (size_t)row * N_ + gc);
            v.x = fexp((v.x - m) * invT);
            v.y = fexp((v.y - m) * invT);
            v.z = fexp((v.z - m) * invT);
            v.w = fexp((v.w - m) * invT);
            ls = (v.x + v.y) + (v.z + v.w);
            __half hx = __float2half_rn(v.x), hy = __float2half_rn(v.y);
            __half hz = __float2half_rn(v.z), hw = __float2half_rn(v.w);
            uh = make_uint2(pkh(hx, hy), pkh(hz, hw));
            ul = make_uint2(pkh(__float2half_rn(v.x - __half2float(hx)),
                                __float2half_rn(v.y - __half2float(hy))),
                            pkh(__float2half_rn(v.z - __half2float(hz)),
                                __float2half_rn(v.w - __half2float(hw))));
        }
        *(uint2*)(g_e_hi + (size_t)row * NPAD + gc) = uh;
        *(uint2*)(g_e_lo + (size_t)row * NPAD + gc) = ul;
    }
    __shared__ float sm[256];
    sm[tid] = ls; __syncthreads();
    for (int s = 128; s > 0; s >>= 1) {
        if (tid < s) sm[tid] += sm[tid + s];
        __syncthreads();
    }
    if (tid == 0) g_psum[(size_t)row * NCH + blockIdx.x] = sm[0];
}

// ================= kernel: per-row 1/sum =================
__global__ __launch_bounds__(256)
void rowsum_kernel()
{
    const int row = blockIdx.x * 256 + threadIdx.x;
    if (row < B_) {
        float s = 0.f;
        for (int c = 0; c < NCH; c++) s += g_psum[(size_t)row * NCH + c];
        g_rinv[row] = 1.f / s;
    }
}

// ===== kernel: pred via mma.sync split-K; writes final fp32 weights from smem =====
__global__ __launch_bounds__(256, 1)
void pred_kernel(float* __restrict__ Wout)
{
    extern __shared__ __align__(16) char dsm_raw[];
    __shared__ float s_inv[BM];
    char* dynPtr = (char*)(((uintptr_t)dsm_raw + 1023) & ~(uintptr_t)1023);
    const uint32_t dynBase = su(dynPtr);
    const int tid = threadIdx.x, wid = tid >> 5, t = tid & 31;
    const int warpM = wid >> 2, warpN = wid & 3;
    const int rowBase = blockIdx.y * BM;
    const int kBase = blockIdx.x * KC2;
    const int nst = (min(kBase + KC2, NPAD) - kBase) / KCH;   // 16 or 12

    if (tid < BM) s_inv[tid] = g_rinv[rowBase + tid];

    auto loadStage = [&](int st, int sidx) {
        const int k0 = kBase + sidx * KCH;
        const uint32_t sb = dynBase + st * STAGEB;
#pragma unroll
        for (int i = 0; i < 4; i++) {
            int lin = tid + i * 256;
            int row = lin >> 3, c16 = lin & 7;
            uint32_t off = (uint32_t)(row * 128 + c16 * 16) ^ (uint32_t)((row & 7) * 16);
            cp16(sb + off,             g_e_hi + (size_t)(rowBase + row) * NPAD + k0 + c16 * 8);
            cp16(sb + TILEB + off,     g_e_lo + (size_t)(rowBase + row) * NPAD + k0 + c16 * 8);
            cp16(sb + 2 * TILEB + off, g_aT_hi + (size_t)row * NPAD + k0 + c16 * 8);
            cp16(sb + 3 * TILEB + off, g_aT_lo + (size_t)row * NPAD + k0 + c16 * 8);
        }
        cpcommit();
    };

    const uint32_t xorv = (uint32_t)((t & 7) * 16);
    uint32_t aOff[4], bOff[4];
#pragma unroll
    for (int mt = 0; mt < 4; mt++) {
        int row = warpM * 64 + mt * 16 + (t & 15);
        aOff[mt] = (uint32_t)(row * 128 + (t >> 4) * 16);
    }
#pragma unroll
    for (int nt = 0; nt < 4; nt++) {
        int row = warpN * 32 + nt * 8 + (t & 7);
        bOff[nt] = (uint32_t)(row * 128 + ((t >> 3) & 1) * 16);
    }

    float acc[4][4][4];
#pragma unroll
    for (int mt = 0; mt < 4; mt++)
#pragma unroll
        for (int nt = 0; nt < 4; nt++)
#pragma unroll
            for (int j = 0; j < 4; j++) acc[mt][nt][j] = 0.f;

    loadStage(0, 0);
    loadStage(1, 1);

    for (int s = 0; s < nst; s++) {
        const int bb = s & 1;
        if (s == nst - 1) cpwait0(); else cpwait1();
        __syncthreads();
        const uint32_t sb = dynBase + bb * STAGEB;
#pragma unroll
        for (int k16 = 0; k16 < 4; k16++) {
            uint32_t ah[4][4], al[4][4], bh[4][2], bl[4][2];
#pragma unroll
            for (int mt = 0; mt < 4; mt++) {
                uint32_t o = (aOff[mt] + k16 * 32) ^ xorv;
                LDSM4(ah[mt], sb + o);
                LDSM4(al[mt], sb + TILEB + o);
            }
#pragma unroll
            for (int nt = 0; nt < 4; nt++) {
                uint32_t o = (bOff[nt] + k16 * 32) ^ xorv;
                LDSM2(bh[nt], sb + 2 * TILEB + o);
                LDSM2(bl[nt], sb + 3 * TILEB + o);
            }
#pragma unroll
            for (int mt = 0; mt < 4; mt++)
#pragma unroll
                for (int nt = 0; nt < 4; nt++) {
                    MMA16816(acc[mt][nt], ah[mt], bh[nt]);
                    MMA16816(acc[mt][nt], ah[mt], bl[nt]);
                    MMA16816(acc[mt][nt], al[mt], bh[nt]);
                }
        }
        // final weights: w = (e_hi + e_lo) * inv, read from this stage's smem tiles
        // full tile = 128 rows x 64 cols: 1024 (row,c16) entries -> i < 4
        {
            char* eb = dynPtr + bb * STAGEB;
#pragma unroll
            for (int i = 0; i < 4; i++) {
                int lin = tid + i * 256;
                int row = lin >> 3, c16 = lin & 7;
                int gc0 = kBase + s * KCH + c16 * 8;
                if (gc0 < N_) {
                    uint32_t off = (uint32_t)(row * 128 + c16 * 16) ^ (uint32_t)((row & 7) * 16);
                    uint4 uh = *(const uint4*)(eb + off);
                    uint4 ul = *(const uint4*)(eb + TILEB + off);
                    const float inv = s_inv[row];
                    float w[8];
                    const __half2* ph = (const __half2*)&uh;
                    const __half2* pl = (const __half2*)&ul;
#pragma unroll
                    for (int p = 0; p < 4; p++) {
                        float2 fh = __half22float2(ph[p]);
                        float2 fl = __half22float2(pl[p]);
                        w[2 * p + 0] = (fh.x + fl.x) * inv;
                        w[2 * p + 1] = (fh.y + fl.y) * inv;
                    }
                    float* dst = Wout + (size_t)(rowBase + row) * N_ + gc0;
                    *(float4*)dst       = make_float4(w[0], w[1], w[2], w[3]);
                    *(float4*)(dst + 4) = make_float4(w[4], w[5], w[6], w[7]);
                }
            }
        }
        __syncthreads();
        if (s + 2 < nst) loadStage(bb, s + 2);
    }

    // store split-K partials (unnormalized)
    float* pp = g_ppred + (size_t)blockIdx.x * (B_ * HA_);
    const int qr = t >> 2, qc = (t & 3) * 2;
#pragma unroll
    for (int mt = 0; mt < 4; mt++)
#pragma unroll
        for (int h = 0; h < 2; h++) {
            const int row = rowBase + warpM * 64 + mt * 16 + qr + h * 8;
#pragma unroll
            for (int nt = 0; nt < 4; nt++) {
                const int col = warpN * 32 + nt * 8 + qc;
                *(float2*)(pp + (size_t)row * HA_ + col) =
                    make_float2(acc[mt][nt][h * 2 + 0], acc[mt][nt][h * 2 + 1]);
            }
        }
}

// ================= kernel: split-K reduction (normalizes) =================
__global__ __launch_bounds__(256)
void predsum_kernel(float* __restrict__ outPred)
{
    const int idx = blockIdx.x * 256 + threadIdx.x;
    if (idx < B_ * HA_) {
        float s = 0.f;
        for (int t = 0; t < SPL2; t++)
            s += g_ppred[(size_t)t * (B_ * HA_) + idx];
        outPred[idx] = s * g_rinv[idx >> 7];
    }
}

// ================= launch =================
extern "C" void kernel_launch(void* const* d_in, const int* in_sizes, int n_in,
                              void* d_out, int out_size)
{
    const float*     query_obs     = (const float*)d_in[0];
    const long long* query_indices = (const long long*)d_in[1];
    const float*     W_enc         = (const float*)d_in[2];
    const float*     train_obs     = (const float*)d_in[3];
    const float*     train_actions = (const float*)d_in[4];
    const float*     logT          = (const float*)d_in[5];

    float* out_pred = (float*)d_out;
    float* out_w    = (float*)d_out + (size_t)B_ * HA_;

    __half *zth, *ztl, *zqh, *zql;
    cudaGetSymbolAddress((void**)&zth, g_zt_hi);
    cudaGetSymbolAddress((void**)&ztl, g_zt_lo);
    cudaGetSymbolAddress((void**)&zqh, g_zq_hi);
    cudaGetSymbolAddress((void**)&zql, g_zq_lo);

    cudaFuncSetAttribute(encode_kernel, cudaFuncAttributeMaxDynamicSharedMemorySize, DYNSM);
    cudaFuncSetAttribute(sim_kernel, cudaFuncAttributeMaxDynamicSharedMemorySize, DYNSM);
    cudaFuncSetAttribute(pred_kernel, cudaFuncAttributeMaxDynamicSharedMemorySize, DYNSM);

    dim3 blk(256);
    dim3 tsp(32, 8);

    prep_kernel<<<1, 1>>>(logT);
    wsplit_kernel<<<dim3(D_ / 32, F_ / 32), tsp>>>(W_enc);
    atsplit_kernel<<<dim3(NPAD / 32, HA_ / 32), tsp>>>(train_actions);
    encode_kernel<<<dim3(F_ / 128, NPAD / BM), blk, DYNSM>>>(train_obs, zth, ztl, N_);
    encode_kernel<<<dim3(F_ / 128, B_ / BM), blk, DYNSM>>>(query_obs, zqh, zql, B_);
    sim_kernel<<<dim3(NT_SIM, B_ / BM), blk, DYNSM>>>(query_indices, out_w);
    rowmax_kernel<<<B_, blk>>>();
    exp_kernel<<<dim3(NCH, B_), blk>>>(out_w);
    rowsum_kernel<<<(B_ + 255) / 256, blk>>>();
    pred_kernel<<<dim3(SPL2, B_ / BM), blk, DYNSM>>>(out_w);
    predsum_kernel<<<(B_ * HA_ + 255) / 256, blk>>>(out_pred);
}